// round 14
// baseline (speedup 1.0000x reference)
#include <cuda_runtime.h>
#include <cuda_bf16.h>
#include <cstdint>

#define BATCH 16384
#define LSEQ  256
#define CH    32
#define EPSBN 1e-5
#define LOG2PI 1.8378770664093453f

typedef unsigned long long ull;

// ---------------- scratch (device-global; no runtime alloc allowed) -------
__device__ float  g_buf1[(size_t)BATCH*CH*LSEQ];   // conv1 output (pre-BN)
__device__ float  g_buf2[(size_t)BATCH*CH*LSEQ];   // h1 (pre-BN)
__device__ float  g_buf3[(size_t)BATCH*CH*LSEQ];   // h2 (pre-BN)
__device__ float  g_ctx [(size_t)BATCH*64];        // context vectors
__device__ double g_stat[3][2][32];                // [stage][sum|sumsq][channel]
__device__ uint2  g_frag[2][2][768];               // [pass][wh|wl][(ks6*4+tn)*32+lane]

// ---------------- packed fp32x2 helpers (FFMA2, conv1/coupling) ------------
__device__ __forceinline__ ull pk(float lo, float hi){
    ull r; asm("mov.b64 %0, {%1,%2};" : "=l"(r) : "f"(lo), "f"(hi)); return r;
}
__device__ __forceinline__ void upk(ull v, float& lo, float& hi){
    asm("mov.b64 {%0,%1}, %2;" : "=f"(lo), "=f"(hi) : "l"(v));
}
__device__ __forceinline__ void ffma2_acc(ull& a, ull b, ull c){
    asm("fma.rn.f32x2 %0, %1, %2, %0;" : "+l"(a) : "l"(b), "l"(c));
}
__device__ __forceinline__ float wred32(float v){
#pragma unroll
    for (int o = 16; o > 0; o >>= 1) v += __shfl_xor_sync(0xffffffffu, v, o);
    return v;
}
__device__ __forceinline__ uint32_t smem_u32(const void* p){
    uint32_t a;
    asm("{ .reg .u64 t; cvta.to.shared.u64 t, %1; cvt.u32.u64 %0, t; }" : "=r"(a) : "l"(p));
    return a;
}

// ---------------- warp-MMA helpers (baseline PTX, works on sm_103) --------
#define LDMATRIX_X4(a0,a1,a2,a3, addr) \
    asm volatile("ldmatrix.sync.aligned.m8n8.x4.shared.b16 {%0,%1,%2,%3}, [%4];" \
        : "=r"(a0), "=r"(a1), "=r"(a2), "=r"(a3) : "r"(addr))
#define LDS64V(x0,x1, addr) \
    asm volatile("ld.shared.v2.u32 {%0,%1}, [%2];" : "=r"(x0), "=r"(x1) : "r"(addr))
#define MMA16816(d, a0,a1,a2,a3, b0,b1) \
    asm volatile("mma.sync.aligned.m16n8k16.row.col.f32.bf16.bf16.f32 " \
        "{%0,%1,%2,%3}, {%4,%5,%6,%7}, {%8,%9}, {%0,%1,%2,%3};" \
        : "+f"((d)[0]), "+f"((d)[1]), "+f"((d)[2]), "+f"((d)[3]) \
        : "r"(a0), "r"(a1), "r"(a2), "r"(a3), "r"(b0), "r"(b1))

// x buffer: 131 rows x 144 bytes (32 xh bf16 | 32 xl bf16, 16B pad)
#define STRXB 144
// smem byte offsets for k_rbmma (R11 layout)
#define SMX    0            // 131*144 = 18864
#define SMWHF  18864        // 768 uint2 = 6144
#define SMWLF  25008        // 6144
#define SMSC   31152        // sc[32], sh[32], cbs[32] = 384
#define SMRED  31536        // redS[8][32], redQ[8][32] = 2048
#define SM_TOTAL_M 33584

// ---------------- K0: zero stats + pre-pack B fragments --------------------
__global__ void k_prep(const float* __restrict__ w1, const float* __restrict__ w2){
    const int t = threadIdx.x;
    if (t < 192) (&g_stat[0][0][0])[t] = 0.0;
#pragma unroll 1
    for (int pass = 0; pass < 2; pass++){
        const float* w = pass ? w2 : w1;
        for (int idx = t; idx < 768; idx += 256){
            int ks6 = idx >> 7, rem = idx & 127, tn = rem >> 5, lane = rem & 31;
            int n = tn*8 + (lane >> 2);
            int kb = ks6*16 + (lane & 3)*2;
            float v[4];
#pragma unroll
            for (int e = 0; e < 4; e++){
                int k = kb + (e >> 1)*8 + (e & 1);      // kb, kb+1, kb+8, kb+9
                int i = k & 31, kkb = k >> 5;
                v[e] = w[n*96 + i*3 + kkb];
            }
            uint32_t h0, h1, l0, l1;
            float hh[4], ll[4];
#pragma unroll
            for (int e = 0; e < 4; e++){
                __nv_bfloat16 h = __float2bfloat16(v[e]);
                hh[e] = __bfloat162float(h);
                ll[e] = v[e] - hh[e];
            }
            asm("cvt.rn.bf16x2.f32 %0, %1, %2;" : "=r"(h0) : "f"(hh[1]), "f"(hh[0]));
            asm("cvt.rn.bf16x2.f32 %0, %1, %2;" : "=r"(h1) : "f"(hh[3]), "f"(hh[2]));
            asm("cvt.rn.bf16x2.f32 %0, %1, %2;" : "=r"(l0) : "f"(ll[1]), "f"(ll[0]));
            asm("cvt.rn.bf16x2.f32 %0, %1, %2;" : "=r"(l1) : "f"(ll[3]), "f"(ll[2]));
            g_frag[pass][0][idx] = make_uint2(h0, h1);
            g_frag[pass][1][idx] = make_uint2(l0, l1);
        }
    }
}

// ---------------- K1: conv1 (4->32, k=5, SAME) + bias, stats stage 0 -------
__global__ __launch_bounds__(128) void k_conv1(const float* __restrict__ curve,
                                               const float* __restrict__ w,
                                               const float* __restrict__ bias){
    const int b = blockIdx.x;
    const int t = threadIdx.x;
    extern __shared__ ull smu[];
    ull*   wd  = smu;                     // dup weights: ull[(i*32+c)*8 + k], 1024
    float* cbs = (float*)(wd + 1024);
    float* xin = cbs + 32;                // 4*272
    float* redS= xin + 4*272;
    float* redQ= redS + 32;

    if (t < 32) cbs[t] = bias[t];
    for (int idx = t; idx < 4*272; idx += 128){
        int i = idx / 272, p = idx - i*272, l = p - 2;
        xin[idx] = (l >= 0 && l < LSEQ) ? curve[((size_t)b*4 + i)*LSEQ + l] : 0.f;
    }
    for (int idx = t; idx < 4*32*8; idx += 128){
        int i = idx >> 8, rem = idx & 255, c = rem >> 3, k = rem & 7;
        float v = (k < 5) ? w[c*20 + i*5 + k] : 0.f;
        ((float2*)wd)[idx] = make_float2(v, v);
    }
    __syncthreads();

    const int wrp = t >> 5, lane = t & 31;
    const int c0 = wrp*8, l0 = lane*8;

    ull A[8][4];
#pragma unroll
    for (int cc = 0; cc < 8; cc++){
        float cb = cbs[c0 + cc];
#pragma unroll
        for (int p = 0; p < 4; p++) A[cc][p] = pk(cb, cb);
    }
#pragma unroll
    for (int i = 0; i < 4; i++){
        const float* xb = xin + i*272 + l0;
        float4 u0 = *(const float4*)(xb);
        float4 u1 = *(const float4*)(xb + 4);
        float4 u2 = *(const float4*)(xb + 8);
        float xm[12] = {u0.x,u0.y,u0.z,u0.w, u1.x,u1.y,u1.z,u1.w, u2.x,u2.y,u2.z,u2.w};
        ull P[11];
#pragma unroll
        for (int m = 0; m < 11; m++) P[m] = pk(xm[m], xm[m+1]);
        const ull* wp = wd + (i*32 + c0)*8;
#pragma unroll
        for (int cc = 0; cc < 8; cc++){
            ulonglong2 W01 = *(const ulonglong2*)(wp + cc*8);
            ulonglong2 W23 = *(const ulonglong2*)(wp + cc*8 + 2);
            ull W4 = wp[cc*8 + 4];
#pragma unroll
            for (int p = 0; p < 4; p++){
                ffma2_acc(A[cc][p], P[2*p+0], W01.x);
                ffma2_acc(A[cc][p], P[2*p+1], W01.y);
                ffma2_acc(A[cc][p], P[2*p+2], W23.x);
                ffma2_acc(A[cc][p], P[2*p+3], W23.y);
                ffma2_acc(A[cc][p], P[2*p+4], W4);
            }
        }
    }

    float* outp = g_buf1 + (size_t)b*CH*LSEQ;
#pragma unroll
    for (int cc = 0; cc < 8; cc++){
        float v[8];
#pragma unroll
        for (int p = 0; p < 4; p++) upk(A[cc][p], v[2*p], v[2*p+1]);
        int c = c0 + cc;
        *(float4*)(outp + c*LSEQ + l0)     = make_float4(v[0],v[1],v[2],v[3]);
        *(float4*)(outp + c*LSEQ + l0 + 4) = make_float4(v[4],v[5],v[6],v[7]);
        float s = 0.f, q = 0.f;
#pragma unroll
        for (int m = 0; m < 8; m++){ s += v[m]; q += v[m]*v[m]; }
        s = wred32(s); q = wred32(q);
        if (lane == 0){ redS[c] = s; redQ[c] = q; }
    }
    __syncthreads();
    if (t < 32){
        atomicAdd(&g_stat[0][0][t], (double)redS[t]);
        atomicAdd(&g_stat[0][1][t], (double)redQ[t]);
    }
}

// ---------------- K2/K3: bn+relu -> conv(32->32,k3) via HMMA (R11 config) --
// CTA = half sample (M=128 rows), 256 threads, 4 CTAs/SM.
__global__ __launch_bounds__(256, 4) void k_rbmma(int pass,
                                               const float* __restrict__ gam,
                                               const float* __restrict__ bet,
                                               const float* __restrict__ cbias){
    const int b = blockIdx.x >> 1;
    const int lbase = (blockIdx.x & 1) * 128;
    const int t = threadIdx.x;
    const int lane = t & 31, wrp = t >> 5;
    const float* bufIn = (pass == 0) ? g_buf1 : g_buf2;
    float* bufOut = (pass == 0) ? g_buf2 : g_buf3;
    const int stIn = pass, stOut = pass + 1;

    extern __shared__ char smc[];
    const uint32_t smb = smem_u32(smc);
    float* sc  = (float*)(smc + SMSC);
    float* sh  = sc + 32;
    float* cbs = sh + 32;
    float* redS= (float*)(smc + SMRED);
    float* redQ= redS + 256;

    if (t < 32){
        const double N = (double)BATCH * (double)LSEQ;
        double S = g_stat[stIn][0][t], Q = g_stat[stIn][1][t];
        double m = S / N, v = Q / N - m*m;
        double s = (double)gam[t] / sqrt(v + EPSBN);
        sc[t] = (float)s;
        sh[t] = (float)((double)bet[t] - m*s);
        cbs[t] = cbias[t];
    }
    {
        const uint4* src = (const uint4*)&g_frag[pass][0][0];
        uint4* dst = (uint4*)(smc + SMWHF);
#pragma unroll
        for (int i = 0; i < 3; i++) dst[t + i*256] = src[t + i*256];
    }
    __syncthreads();

    {
        const float* inp = bufIn + (size_t)b*CH*LSEQ;
        for (int idx = t; idx < 16*130; idx += 256){
            int ip = idx / 130, lp = idx - ip*130;
            int i = ip*2;
            int l = lbase + lp - 1;
            float y0 = 0.f, y1 = 0.f;
            if (l >= 0 && l < LSEQ){
                y0 = fmaxf(sc[i]*inp[i*LSEQ + l] + sh[i], 0.f);
                y1 = fmaxf(sc[i+1]*inp[(i+1)*LSEQ + l] + sh[i+1], 0.f);
            }
            uint32_t hp;
            asm("cvt.rn.bf16x2.f32 %0, %1, %2;" : "=r"(hp) : "f"(y1), "f"(y0));
            float h0 = __uint_as_float(hp << 16);
            float h1 = __uint_as_float(hp & 0xffff0000u);
            float e0 = y0 - h0, e1 = y1 - h1;
            uint32_t lp2;
            asm("cvt.rn.bf16x2.f32 %0, %1, %2;" : "=r"(lp2) : "f"(e1), "f"(e0));
            *(uint32_t*)(smc + SMX + lp*STRXB + i*2)      = hp;
            *(uint32_t*)(smc + SMX + lp*STRXB + 64 + i*2) = lp2;
        }
    }
    __syncthreads();

    const int m0 = wrp*16;
    float d[4][4];
#pragma unroll
    for (int tn = 0; tn < 4; tn++)
#pragma unroll
        for (int e = 0; e < 4; e++) d[tn][e] = 0.f;

    const uint32_t axbase = smb + SMX +
        (uint32_t)((m0 + (lane & 15))*STRXB + ((lane & 16) ? 16 : 0));
    const uint32_t bwh = smb + SMWHF + (uint32_t)(lane*8);
    const uint32_t bwl = smb + SMWLF + (uint32_t)(lane*8);

#pragma unroll
    for (int ks6 = 0; ks6 < 6; ks6++){
        const int kk = ks6 >> 1, kc = ks6 & 1;
        const uint32_t aaddr = axbase + (uint32_t)(kk*STRXB + kc*32);
        uint32_t ah0,ah1,ah2,ah3, al0,al1,al2,al3;
        LDMATRIX_X4(ah0,ah1,ah2,ah3, aaddr);          // xh
        LDMATRIX_X4(al0,al1,al2,al3, aaddr + 64);     // xl
        uint32_t b00,b01,b10,b11,b20,b21,b30,b31;
        LDS64V(b00,b01, bwh + (uint32_t)((ks6*4 + 0)*256));
        LDS64V(b10,b11, bwh + (uint32_t)((ks6*4 + 1)*256));
        LDS64V(b20,b21, bwh + (uint32_t)((ks6*4 + 2)*256));
        LDS64V(b30,b31, bwh + (uint32_t)((ks6*4 + 3)*256));
        MMA16816(d[0], ah0,ah1,ah2,ah3, b00,b01);     // xh @ wh
        MMA16816(d[1], ah0,ah1,ah2,ah3, b10,b11);
        MMA16816(d[2], ah0,ah1,ah2,ah3, b20,b21);
        MMA16816(d[3], ah0,ah1,ah2,ah3, b30,b31);
        MMA16816(d[0], al0,al1,al2,al3, b00,b01);     // xl @ wh
        MMA16816(d[1], al0,al1,al2,al3, b10,b11);
        MMA16816(d[2], al0,al1,al2,al3, b20,b21);
        MMA16816(d[3], al0,al1,al2,al3, b30,b31);
        LDS64V(b00,b01, bwl + (uint32_t)((ks6*4 + 0)*256));
        LDS64V(b10,b11, bwl + (uint32_t)((ks6*4 + 1)*256));
        LDS64V(b20,b21, bwl + (uint32_t)((ks6*4 + 2)*256));
        LDS64V(b30,b31, bwl + (uint32_t)((ks6*4 + 3)*256));
        MMA16816(d[0], ah0,ah1,ah2,ah3, b00,b01);     // xh @ wl
        MMA16816(d[1], ah0,ah1,ah2,ah3, b10,b11);
        MMA16816(d[2], ah0,ah1,ah2,ah3, b20,b21);
        MMA16816(d[3], ah0,ah1,ah2,ah3, b30,b31);
    }

    float* outp = bufOut + (size_t)b*CH*LSEQ + lbase;
    float ps[8], pq[8];
#pragma unroll
    for (int j = 0; j < 8; j++){ ps[j] = 0.f; pq[j] = 0.f; }
    {
        int r0 = m0 + (lane >> 2);
#pragma unroll
        for (int tn = 0; tn < 4; tn++){
            int c0 = tn*8 + (lane & 3)*2;
            float v00 = d[tn][0] + cbs[c0];
            float v01 = d[tn][1] + cbs[c0+1];
            float v10 = d[tn][2] + cbs[c0];
            float v11 = d[tn][3] + cbs[c0+1];
            outp[c0*LSEQ + r0]         = v00;
            outp[(c0+1)*LSEQ + r0]     = v01;
            outp[c0*LSEQ + r0 + 8]     = v10;
            outp[(c0+1)*LSEQ + r0 + 8] = v11;
            ps[tn*2+0] += v00 + v10;  pq[tn*2+0] += v00*v00 + v10*v10;
            ps[tn*2+1] += v01 + v11;  pq[tn*2+1] += v01*v01 + v11*v11;
        }
    }
#pragma unroll
    for (int j = 0; j < 8; j++){
#pragma unroll
        for (int o = 4; o < 32; o <<= 1){
            ps[j] += __shfl_xor_sync(0xffffffffu, ps[j], o);
            pq[j] += __shfl_xor_sync(0xffffffffu, pq[j], o);
        }
    }
    if (lane < 4){
#pragma unroll
        for (int tn = 0; tn < 4; tn++){
#pragma unroll
            for (int p = 0; p < 2; p++){
                int c = tn*8 + lane*2 + p;
                redS[wrp*32 + c] = ps[tn*2+p];
                redQ[wrp*32 + c] = pq[tn*2+p];
            }
        }
    }
    __syncthreads();
    if (t < 32){
        double S = 0.0, Q = 0.0;
#pragma unroll
        for (int wI = 0; wI < 8; wI++){ S += redS[wI*32 + t]; Q += redQ[wI*32 + t]; }
        atomicAdd(&g_stat[stOut][0][t], S);
        atomicAdd(&g_stat[stOut][1][t], Q);
    }
}

// ---------------- K4: bn0+relu, bn2, residual+relu, mean-pool, linear+tanh -
__global__ __launch_bounds__(256) void k_pool_ctx(const float* __restrict__ gamma1,
                                                  const float* __restrict__ beta1,
                                                  const float* __restrict__ gamma3,
                                                  const float* __restrict__ beta3,
                                                  const float* __restrict__ lin_w,
                                                  const float* __restrict__ lin_b){
    const int b = blockIdx.x;
    const int t = threadIdx.x;
    __shared__ float sc0[32], sh0[32], sc2[32], sh2[32];
    __shared__ float red[32][8];
    __shared__ float pooled[32];

    if (t < 32){
        const double N = (double)BATCH * (double)LSEQ;
        { double S = g_stat[0][0][t], Q = g_stat[0][1][t];
          double m = S/N, v = Q/N - m*m;
          double s = (double)gamma1[t] / sqrt(v + EPSBN);
          sc0[t] = (float)s; sh0[t] = (float)((double)beta1[t] - m*s); }
        { double S = g_stat[2][0][t], Q = g_stat[2][1][t];
          double m = S/N, v = Q/N - m*m;
          double s = (double)gamma3[t] / sqrt(v + EPSBN);
          sc2[t] = (float)s; sh2[t] = (float)((double)beta3[t] - m*s); }
    }
    __syncthreads();

    const float* p1 = g_buf1 + (size_t)b*CH*LSEQ;
    const float* p2 = g_buf3 + (size_t)b*CH*LSEQ;
    const int wid = t >> 5, lane = t & 31;
#pragma unroll 1
    for (int c = 0; c < 32; c++){
        float y1 = p1[c*LSEQ + t];
        float h2 = p2[c*LSEQ + t];
        float x1 = fmaxf(sc0[c]*y1 + sh0[c], 0.f);
        float x2 = fmaxf(sc2[c]*h2 + sh2[c] + x1, 0.f);
        float s = wred32(x2);
        if (lane == 0) red[c][wid] = s;
    }
    __syncthreads();
    if (t < 32){
        float s = 0.f;
#pragma unroll
        for (int wI = 0; wI < 8; wI++) s += red[t][wI];
        pooled[t] = s * (1.f/(float)LSEQ);
    }
    __syncthreads();
    if (t < 64){
        float acc = lin_b[t];
#pragma unroll
        for (int c = 0; c < 32; c++) acc += pooled[c]*lin_w[c*64 + t];
        g_ctx[(size_t)b*64 + t] = tanhf(acc);
    }
}

// ---------------- K5: 10 coupling layers, 32 rows per block ---------------
// grid = BATCH/32 = 512 blocks; smem ~47KB -> 4 CTAs/SM resident
__global__ __launch_bounds__(256) void k_coupling(const float* __restrict__ zin,
                                                  const float* __restrict__ W1,
                                                  const float* __restrict__ B1w,
                                                  const float* __restrict__ W2,
                                                  const float* __restrict__ B2w,
                                                  const float* __restrict__ W3,
                                                  const float* __restrict__ B3w,
                                                  float* __restrict__ outp){
    const int t = threadIdx.x;
    const int rowBase = blockIdx.x * 32;
    extern __shared__ float sm[];
    float* nin = sm;                 // 32*76
    float* hA  = nin + 32*76;        // 32*132
    float* hB  = hA  + 32*132;       // 32*132
    float* zz  = hB  + 32*132;       // 32*12
    float* ob  = zz  + 32*12;        // 32*20
    float* ldv = ob  + 32*20;        // 32

    for (int idx = t; idx < 32*9; idx += 256){
        int r = idx/9, j = idx - r*9;
        zz[r*12 + j] = zin[(size_t)(rowBase + r)*9 + j];
    }
    for (int idx = t; idx < 32*64; idx += 256){
        int r = idx >> 6, j = idx & 63;
        nin[r*76 + 9 + j] = g_ctx[(size_t)(rowBase + r)*64 + j];
    }
    if (t < 32) ldv[t] = 0.f;
    __syncthreads();

    const int jc = t & 31;           // 4 output columns: 4*jc .. 4*jc+3
    const int r0 = (t >> 5) * 4;     // 4 rows per warp

    for (int layer = 0; layer < 10; ++layer){
        if (t < 32){
#pragma unroll
            for (int j = 0; j < 9; j++){
                float m = (((j + layer) & 1) == 0) ? 1.f : 0.f;
                nin[t*76 + j] = zz[t*12 + j] * m;
            }
        }
        __syncthreads();

        // GEMM1: hA = relu(nin[32x73] @ W1[73x128] + b1)  (packed f32x2)
        {
            const float* Wl = W1 + (size_t)layer*73*128;
            float4 bb = *(const float4*)(B1w + layer*128 + 4*jc);
            ull acc[4][2];
#pragma unroll
            for (int r = 0; r < 4; r++){ acc[r][0] = pk(bb.x, bb.y); acc[r][1] = pk(bb.z, bb.w); }
#pragma unroll 2
            for (int i = 0; i < 73; i++){
                ulonglong2 wv = *(const ulonglong2*)(Wl + i*128 + 4*jc);
#pragma unroll
                for (int r = 0; r < 4; r++){
                    float x = nin[(r0 + r)*76 + i];
                    ull xx = pk(x, x);
                    ffma2_acc(acc[r][0], xx, wv.x);
                    ffma2_acc(acc[r][1], xx, wv.y);
                }
            }
#pragma unroll
            for (int r = 0; r < 4; r++){
                float v0,v1,v2,v3;
                upk(acc[r][0], v0, v1); upk(acc[r][1], v2, v3);
                *(float4*)(hA + (r0 + r)*132 + 4*jc) =
                    make_float4(fmaxf(v0,0.f), fmaxf(v1,0.f), fmaxf(v2,0.f), fmaxf(v3,0.f));
            }
        }
        __syncthreads();

        // GEMM2: hB = relu(hA[32x128] @ W2[128x128] + b2)  (packed f32x2)
        {
            const float* Wl = W2 + (size_t)layer*128*128;
            float4 bb = *(const float4*)(B2w + layer*128 + 4*jc);
            ull acc[4][2];
#pragma unroll
            for (int r = 0; r < 4; r++){ acc[r][0] = pk(bb.x, bb.y); acc[r][1] = pk(bb.z, bb.w); }
#pragma unroll 2
            for (int i = 0; i < 128; i++){
                ulonglong2 wv = *(const ulonglong2*)(Wl + i*128 + 4*jc);
#pragma unroll
                for (int r = 0; r < 4; r++){
                    float x = hA[(r0 + r)*132 + i];
                    ull xx = pk(x, x);
                    ffma2_acc(acc[r][0], xx, wv.x);
                    ffma2_acc(acc[r][1], xx, wv.y);
                }
            }
#pragma unroll
            for (int r = 0; r < 4; r++){
                float v0,v1,v2,v3;
                upk(acc[r][0], v0, v1); upk(acc[r][1], v2, v3);
                *(float4*)(hB + (r0 + r)*132 + 4*jc) =
                    make_float4(fmaxf(v0,0.f), fmaxf(v1,0.f), fmaxf(v2,0.f), fmaxf(v3,0.f));
            }
        }
        __syncthreads();

        // GEMM3: ob = hB[32x128] @ W3[128x18] + b3 (8 threads per row)
        {
            const float* Wl = W3 + (size_t)layer*128*18;
            const int r = t >> 3, q = t & 7;
            float acc[3] = {0.f, 0.f, 0.f};
#pragma unroll 2
            for (int i = 0; i < 128; i++){
                float x = hB[r*132 + i];
#pragma unroll
                for (int k = 0; k < 3; k++){
                    int j = q + 8*k;
                    if (j < 18) acc[k] = fmaf(x, __ldg(Wl + i*18 + j), acc[k]);
                }
            }
#pragma unroll
            for (int k = 0; k < 3; k++){
                int j = q + 8*k;
                if (j < 18) ob[r*20 + j] = acc[k] + B3w[layer*18 + j];
            }
        }
        __syncthreads();

        // per-row flow update
        if (t < 32){
            float ldl = ldv[t];
#pragma unroll
            for (int j = 0; j < 9; j++){
                if (((j + layer) & 1) != 0){
                    float s  = tanhf(ob[t*20 + j]);
                    float tt = ob[t*20 + 9 + j];
                    zz[t*12 + j] = zz[t*12 + j]*expf(s) + tt;
                    ldl += s;
                }
            }
            ldv[t] = ldl;
        }
        __syncthreads();
    }

    if (t < 32){
        float lp = 0.f;
#pragma unroll
        for (int j = 0; j < 9; j++){
            float z = zz[t*12 + j];
            lp += LOG2PI + z*z;
        }
        outp[rowBase + t] = ldv[t] - 0.5f*lp;
    }
}

// ---------------- launch ----------------------------------------------------
extern "C" void kernel_launch(void* const* d_in, const int* in_sizes, int n_in,
                              void* d_out, int out_size){
    const float* inputs  = (const float*)d_in[0];
    const float* curve   = (const float*)d_in[1];
    const float* conv1_w = (const float*)d_in[2];
    const float* conv1_b = (const float*)d_in[3];
    const float* bn1_g   = (const float*)d_in[4];
    const float* bn1_b   = (const float*)d_in[5];
    const float* rb_w1   = (const float*)d_in[6];
    const float* rb_b1   = (const float*)d_in[7];
    const float* rb_g1   = (const float*)d_in[8];
    const float* rb_be1  = (const float*)d_in[9];
    const float* rb_w2   = (const float*)d_in[10];
    const float* rb_b2   = (const float*)d_in[11];
    const float* rb_g2   = (const float*)d_in[12];
    const float* rb_be2  = (const float*)d_in[13];
    const float* lin_w   = (const float*)d_in[14];
    const float* lin_b   = (const float*)d_in[15];
    const float* W1      = (const float*)d_in[16];
    const float* B1      = (const float*)d_in[17];
    const float* W2      = (const float*)d_in[18];
    const float* B2      = (const float*)d_in[19];
    const float* W3      = (const float*)d_in[20];
    const float* B3      = (const float*)d_in[21];
    float* out = (float*)d_out;

    const int smem1 = 1024*8 + (32 + 4*272 + 32 + 32) * 4;
    const int smemC = (32*76 + 32*132*2 + 32*12 + 32*20 + 32) * 4;

    cudaFuncSetAttribute(k_conv1,    cudaFuncAttributeMaxDynamicSharedMemorySize, smem1);
    cudaFuncSetAttribute(k_rbmma,    cudaFuncAttributeMaxDynamicSharedMemorySize, SM_TOTAL_M);
    cudaFuncSetAttribute(k_coupling, cudaFuncAttributeMaxDynamicSharedMemorySize, smemC);

    k_prep<<<1, 256>>>(rb_w1, rb_w2);
    k_conv1<<<BATCH, 128, smem1>>>(curve, conv1_w, conv1_b);
    k_rbmma<<<BATCH*2, 256, SM_TOTAL_M>>>(0, bn1_g, bn1_b, rb_b1);
    k_rbmma<<<BATCH*2, 256, SM_TOTAL_M>>>(1, rb_g1, rb_be1, rb_b2);
    k_pool_ctx<<<BATCH, 256>>>(bn1_g, bn1_b, rb_g2, rb_be2, lin_w, lin_b);
    k_coupling<<<BATCH/32, 256, smemC>>>(inputs, W1, B1, W2, B2, W3, B3, out);
}

// round 15
// speedup vs baseline: 1.1922x; 1.1922x over previous
#include <cuda_runtime.h>
#include <cuda_bf16.h>
#include <cstdint>

#define BATCH 16384
#define LSEQ  256
#define CH    32
#define EPSBN 1e-5
#define LOG2PI 1.8378770664093453f

typedef unsigned long long ull;

// ---------------- scratch (device-global; no runtime alloc allowed) -------
__device__ float  g_buf1[(size_t)BATCH*CH*LSEQ];   // conv1 output (pre-BN)
__device__ float  g_buf2[(size_t)BATCH*CH*LSEQ];   // h1 (pre-BN)
__device__ float  g_buf3[(size_t)BATCH*CH*LSEQ];   // h2 (pre-BN)
__device__ float  g_ctx [(size_t)BATCH*64];        // context vectors
__device__ double g_stat[3][2][32];                // [stage][sum|sumsq][channel]
__device__ uint2  g_frag[2][2][768];               // [pass][wh|wl][(ks6*4+tn)*32+lane]

// ---------------- packed fp32x2 helpers (FFMA2, conv1/coupling) ------------
__device__ __forceinline__ ull pk(float lo, float hi){
    ull r; asm("mov.b64 %0, {%1,%2};" : "=l"(r) : "f"(lo), "f"(hi)); return r;
}
__device__ __forceinline__ void upk(ull v, float& lo, float& hi){
    asm("mov.b64 {%0,%1}, %2;" : "=f"(lo), "=f"(hi) : "l"(v));
}
__device__ __forceinline__ void ffma2_acc(ull& a, ull b, ull c){
    asm("fma.rn.f32x2 %0, %1, %2, %0;" : "+l"(a) : "l"(b), "l"(c));
}
__device__ __forceinline__ float wred32(float v){
#pragma unroll
    for (int o = 16; o > 0; o >>= 1) v += __shfl_xor_sync(0xffffffffu, v, o);
    return v;
}
__device__ __forceinline__ uint32_t smem_u32(const void* p){
    uint32_t a;
    asm("{ .reg .u64 t; cvta.to.shared.u64 t, %1; cvt.u32.u64 %0, t; }" : "=r"(a) : "l"(p));
    return a;
}

// ---------------- warp-MMA helpers (baseline PTX, works on sm_103) --------
#define LDMATRIX_X4(a0,a1,a2,a3, addr) \
    asm volatile("ldmatrix.sync.aligned.m8n8.x4.shared.b16 {%0,%1,%2,%3}, [%4];" \
        : "=r"(a0), "=r"(a1), "=r"(a2), "=r"(a3) : "r"(addr))
#define LDS64V(x0,x1, addr) \
    asm volatile("ld.shared.v2.u32 {%0,%1}, [%2];" : "=r"(x0), "=r"(x1) : "r"(addr))
#define MMA16816(d, a0,a1,a2,a3, b0,b1) \
    asm volatile("mma.sync.aligned.m16n8k16.row.col.f32.bf16.bf16.f32 " \
        "{%0,%1,%2,%3}, {%4,%5,%6,%7}, {%8,%9}, {%0,%1,%2,%3};" \
        : "+f"((d)[0]), "+f"((d)[1]), "+f"((d)[2]), "+f"((d)[3]) \
        : "r"(a0), "r"(a1), "r"(a2), "r"(a3), "r"(b0), "r"(b1))

// x buffer: 131 rows x 144 bytes (32 xh bf16 | 32 xl bf16, 16B pad)
#define STRXB 144
// smem byte offsets for k_rbmma (R11 layout)
#define SMX    0            // 131*144 = 18864
#define SMWHF  18864        // 768 uint2 = 6144
#define SMWLF  25008        // 6144
#define SMSC   31152        // sc[32], sh[32], cbs[32] = 384
#define SMRED  31536        // redS[8][32], redQ[8][32] = 2048
#define SM_TOTAL_M 33584

// ---------------- K0: zero stats + pre-pack B fragments --------------------
__global__ void k_prep(const float* __restrict__ w1, const float* __restrict__ w2){
    const int t = threadIdx.x;
    if (t < 192) (&g_stat[0][0][0])[t] = 0.0;
#pragma unroll 1
    for (int pass = 0; pass < 2; pass++){
        const float* w = pass ? w2 : w1;
        for (int idx = t; idx < 768; idx += 256){
            int ks6 = idx >> 7, rem = idx & 127, tn = rem >> 5, lane = rem & 31;
            int n = tn*8 + (lane >> 2);
            int kb = ks6*16 + (lane & 3)*2;
            float v[4];
#pragma unroll
            for (int e = 0; e < 4; e++){
                int k = kb + (e >> 1)*8 + (e & 1);      // kb, kb+1, kb+8, kb+9
                int i = k & 31, kkb = k >> 5;
                v[e] = w[n*96 + i*3 + kkb];
            }
            uint32_t h0, h1, l0, l1;
            float hh[4], ll[4];
#pragma unroll
            for (int e = 0; e < 4; e++){
                __nv_bfloat16 h = __float2bfloat16(v[e]);
                hh[e] = __bfloat162float(h);
                ll[e] = v[e] - hh[e];
            }
            asm("cvt.rn.bf16x2.f32 %0, %1, %2;" : "=r"(h0) : "f"(hh[1]), "f"(hh[0]));
            asm("cvt.rn.bf16x2.f32 %0, %1, %2;" : "=r"(h1) : "f"(hh[3]), "f"(hh[2]));
            asm("cvt.rn.bf16x2.f32 %0, %1, %2;" : "=r"(l0) : "f"(ll[1]), "f"(ll[0]));
            asm("cvt.rn.bf16x2.f32 %0, %1, %2;" : "=r"(l1) : "f"(ll[3]), "f"(ll[2]));
            g_frag[pass][0][idx] = make_uint2(h0, h1);
            g_frag[pass][1][idx] = make_uint2(l0, l1);
        }
    }
}

// ---------------- K1: conv1 (4->32, k=5, SAME) + bias, stats stage 0 -------
__global__ __launch_bounds__(128) void k_conv1(const float* __restrict__ curve,
                                               const float* __restrict__ w,
                                               const float* __restrict__ bias){
    const int b = blockIdx.x;
    const int t = threadIdx.x;
    extern __shared__ ull smu[];
    ull*   wd  = smu;                     // dup weights: ull[(i*32+c)*8 + k], 1024
    float* cbs = (float*)(wd + 1024);
    float* xin = cbs + 32;                // 4*272
    float* redS= xin + 4*272;
    float* redQ= redS + 32;

    if (t < 32) cbs[t] = bias[t];
    for (int idx = t; idx < 4*272; idx += 128){
        int i = idx / 272, p = idx - i*272, l = p - 2;
        xin[idx] = (l >= 0 && l < LSEQ) ? curve[((size_t)b*4 + i)*LSEQ + l] : 0.f;
    }
    for (int idx = t; idx < 4*32*8; idx += 128){
        int i = idx >> 8, rem = idx & 255, c = rem >> 3, k = rem & 7;
        float v = (k < 5) ? w[c*20 + i*5 + k] : 0.f;
        ((float2*)wd)[idx] = make_float2(v, v);
    }
    __syncthreads();

    const int wrp = t >> 5, lane = t & 31;
    const int c0 = wrp*8, l0 = lane*8;

    ull A[8][4];
#pragma unroll
    for (int cc = 0; cc < 8; cc++){
        float cb = cbs[c0 + cc];
#pragma unroll
        for (int p = 0; p < 4; p++) A[cc][p] = pk(cb, cb);
    }
#pragma unroll
    for (int i = 0; i < 4; i++){
        const float* xb = xin + i*272 + l0;
        float4 u0 = *(const float4*)(xb);
        float4 u1 = *(const float4*)(xb + 4);
        float4 u2 = *(const float4*)(xb + 8);
        float xm[12] = {u0.x,u0.y,u0.z,u0.w, u1.x,u1.y,u1.z,u1.w, u2.x,u2.y,u2.z,u2.w};
        ull P[11];
#pragma unroll
        for (int m = 0; m < 11; m++) P[m] = pk(xm[m], xm[m+1]);
        const ull* wp = wd + (i*32 + c0)*8;
#pragma unroll
        for (int cc = 0; cc < 8; cc++){
            ulonglong2 W01 = *(const ulonglong2*)(wp + cc*8);
            ulonglong2 W23 = *(const ulonglong2*)(wp + cc*8 + 2);
            ull W4 = wp[cc*8 + 4];
#pragma unroll
            for (int p = 0; p < 4; p++){
                ffma2_acc(A[cc][p], P[2*p+0], W01.x);
                ffma2_acc(A[cc][p], P[2*p+1], W01.y);
                ffma2_acc(A[cc][p], P[2*p+2], W23.x);
                ffma2_acc(A[cc][p], P[2*p+3], W23.y);
                ffma2_acc(A[cc][p], P[2*p+4], W4);
            }
        }
    }

    float* outp = g_buf1 + (size_t)b*CH*LSEQ;
#pragma unroll
    for (int cc = 0; cc < 8; cc++){
        float v[8];
#pragma unroll
        for (int p = 0; p < 4; p++) upk(A[cc][p], v[2*p], v[2*p+1]);
        int c = c0 + cc;
        *(float4*)(outp + c*LSEQ + l0)     = make_float4(v[0],v[1],v[2],v[3]);
        *(float4*)(outp + c*LSEQ + l0 + 4) = make_float4(v[4],v[5],v[6],v[7]);
        float s = 0.f, q = 0.f;
#pragma unroll
        for (int m = 0; m < 8; m++){ s += v[m]; q += v[m]*v[m]; }
        s = wred32(s); q = wred32(q);
        if (lane == 0){ redS[c] = s; redQ[c] = q; }
    }
    __syncthreads();
    if (t < 32){
        atomicAdd(&g_stat[0][0][t], (double)redS[t]);
        atomicAdd(&g_stat[0][1][t], (double)redQ[t]);
    }
}

// ---------------- K2/K3: bn+relu -> conv(32->32,k3) via HMMA (R11 config) --
__global__ __launch_bounds__(256, 4) void k_rbmma(int pass,
                                               const float* __restrict__ gam,
                                               const float* __restrict__ bet,
                                               const float* __restrict__ cbias){
    const int b = blockIdx.x >> 1;
    const int lbase = (blockIdx.x & 1) * 128;
    const int t = threadIdx.x;
    const int lane = t & 31, wrp = t >> 5;
    const float* bufIn = (pass == 0) ? g_buf1 : g_buf2;
    float* bufOut = (pass == 0) ? g_buf2 : g_buf3;
    const int stIn = pass, stOut = pass + 1;

    extern __shared__ char smc[];
    const uint32_t smb = smem_u32(smc);
    float* sc  = (float*)(smc + SMSC);
    float* sh  = sc + 32;
    float* cbs = sh + 32;
    float* redS= (float*)(smc + SMRED);
    float* redQ= redS + 256;

    if (t < 32){
        const double N = (double)BATCH * (double)LSEQ;
        double S = g_stat[stIn][0][t], Q = g_stat[stIn][1][t];
        double m = S / N, v = Q / N - m*m;
        double s = (double)gam[t] / sqrt(v + EPSBN);
        sc[t] = (float)s;
        sh[t] = (float)((double)bet[t] - m*s);
        cbs[t] = cbias[t];
    }
    {
        const uint4* src = (const uint4*)&g_frag[pass][0][0];
        uint4* dst = (uint4*)(smc + SMWHF);
#pragma unroll
        for (int i = 0; i < 3; i++) dst[t + i*256] = src[t + i*256];
    }
    __syncthreads();

    {
        const float* inp = bufIn + (size_t)b*CH*LSEQ;
        for (int idx = t; idx < 16*130; idx += 256){
            int ip = idx / 130, lp = idx - ip*130;
            int i = ip*2;
            int l = lbase + lp - 1;
            float y0 = 0.f, y1 = 0.f;
            if (l >= 0 && l < LSEQ){
                y0 = fmaxf(sc[i]*inp[i*LSEQ + l] + sh[i], 0.f);
                y1 = fmaxf(sc[i+1]*inp[(i+1)*LSEQ + l] + sh[i+1], 0.f);
            }
            uint32_t hp;
            asm("cvt.rn.bf16x2.f32 %0, %1, %2;" : "=r"(hp) : "f"(y1), "f"(y0));
            float h0 = __uint_as_float(hp << 16);
            float h1 = __uint_as_float(hp & 0xffff0000u);
            float e0 = y0 - h0, e1 = y1 - h1;
            uint32_t lp2;
            asm("cvt.rn.bf16x2.f32 %0, %1, %2;" : "=r"(lp2) : "f"(e1), "f"(e0));
            *(uint32_t*)(smc + SMX + lp*STRXB + i*2)      = hp;
            *(uint32_t*)(smc + SMX + lp*STRXB + 64 + i*2) = lp2;
        }
    }
    __syncthreads();

    const int m0 = wrp*16;
    float d[4][4];
#pragma unroll
    for (int tn = 0; tn < 4; tn++)
#pragma unroll
        for (int e = 0; e < 4; e++) d[tn][e] = 0.f;

    const uint32_t axbase = smb + SMX +
        (uint32_t)((m0 + (lane & 15))*STRXB + ((lane & 16) ? 16 : 0));
    const uint32_t bwh = smb + SMWHF + (uint32_t)(lane*8);
    const uint32_t bwl = smb + SMWLF + (uint32_t)(lane*8);

#pragma unroll
    for (int ks6 = 0; ks6 < 6; ks6++){
        const int kk = ks6 >> 1, kc = ks6 & 1;
        const uint32_t aaddr = axbase + (uint32_t)(kk*STRXB + kc*32);
        uint32_t ah0,ah1,ah2,ah3, al0,al1,al2,al3;
        LDMATRIX_X4(ah0,ah1,ah2,ah3, aaddr);          // xh
        LDMATRIX_X4(al0,al1,al2,al3, aaddr + 64);     // xl
        uint32_t b00,b01,b10,b11,b20,b21,b30,b31;
        LDS64V(b00,b01, bwh + (uint32_t)((ks6*4 + 0)*256));
        LDS64V(b10,b11, bwh + (uint32_t)((ks6*4 + 1)*256));
        LDS64V(b20,b21, bwh + (uint32_t)((ks6*4 + 2)*256));
        LDS64V(b30,b31, bwh + (uint32_t)((ks6*4 + 3)*256));
        MMA16816(d[0], ah0,ah1,ah2,ah3, b00,b01);     // xh @ wh
        MMA16816(d[1], ah0,ah1,ah2,ah3, b10,b11);
        MMA16816(d[2], ah0,ah1,ah2,ah3, b20,b21);
        MMA16816(d[3], ah0,ah1,ah2,ah3, b30,b31);
        MMA16816(d[0], al0,al1,al2,al3, b00,b01);     // xl @ wh
        MMA16816(d[1], al0,al1,al2,al3, b10,b11);
        MMA16816(d[2], al0,al1,al2,al3, b20,b21);
        MMA16816(d[3], al0,al1,al2,al3, b30,b31);
        LDS64V(b00,b01, bwl + (uint32_t)((ks6*4 + 0)*256));
        LDS64V(b10,b11, bwl + (uint32_t)((ks6*4 + 1)*256));
        LDS64V(b20,b21, bwl + (uint32_t)((ks6*4 + 2)*256));
        LDS64V(b30,b31, bwl + (uint32_t)((ks6*4 + 3)*256));
        MMA16816(d[0], ah0,ah1,ah2,ah3, b00,b01);     // xh @ wl
        MMA16816(d[1], ah0,ah1,ah2,ah3, b10,b11);
        MMA16816(d[2], ah0,ah1,ah2,ah3, b20,b21);
        MMA16816(d[3], ah0,ah1,ah2,ah3, b30,b31);
    }

    float* outp = bufOut + (size_t)b*CH*LSEQ + lbase;
    float ps[8], pq[8];
#pragma unroll
    for (int j = 0; j < 8; j++){ ps[j] = 0.f; pq[j] = 0.f; }
    {
        int r0 = m0 + (lane >> 2);
#pragma unroll
        for (int tn = 0; tn < 4; tn++){
            int c0 = tn*8 + (lane & 3)*2;
            float v00 = d[tn][0] + cbs[c0];
            float v01 = d[tn][1] + cbs[c0+1];
            float v10 = d[tn][2] + cbs[c0];
            float v11 = d[tn][3] + cbs[c0+1];
            outp[c0*LSEQ + r0]         = v00;
            outp[(c0+1)*LSEQ + r0]     = v01;
            outp[c0*LSEQ + r0 + 8]     = v10;
            outp[(c0+1)*LSEQ + r0 + 8] = v11;
            ps[tn*2+0] += v00 + v10;  pq[tn*2+0] += v00*v00 + v10*v10;
            ps[tn*2+1] += v01 + v11;  pq[tn*2+1] += v01*v01 + v11*v11;
        }
    }
#pragma unroll
    for (int j = 0; j < 8; j++){
#pragma unroll
        for (int o = 4; o < 32; o <<= 1){
            ps[j] += __shfl_xor_sync(0xffffffffu, ps[j], o);
            pq[j] += __shfl_xor_sync(0xffffffffu, pq[j], o);
        }
    }
    if (lane < 4){
#pragma unroll
        for (int tn = 0; tn < 4; tn++){
#pragma unroll
            for (int p = 0; p < 2; p++){
                int c = tn*8 + lane*2 + p;
                redS[wrp*32 + c] = ps[tn*2+p];
                redQ[wrp*32 + c] = pq[tn*2+p];
            }
        }
    }
    __syncthreads();
    if (t < 32){
        double S = 0.0, Q = 0.0;
#pragma unroll
        for (int wI = 0; wI < 8; wI++){ S += redS[wI*32 + t]; Q += redQ[wI*32 + t]; }
        atomicAdd(&g_stat[stOut][0][t], S);
        atomicAdd(&g_stat[stOut][1][t], Q);
    }
}

// ---------------- K4: bn0+relu, bn2, residual+relu, mean-pool, linear+tanh -
__global__ __launch_bounds__(256) void k_pool_ctx(const float* __restrict__ gamma1,
                                                  const float* __restrict__ beta1,
                                                  const float* __restrict__ gamma3,
                                                  const float* __restrict__ beta3,
                                                  const float* __restrict__ lin_w,
                                                  const float* __restrict__ lin_b){
    const int b = blockIdx.x;
    const int t = threadIdx.x;
    __shared__ float sc0[32], sh0[32], sc2[32], sh2[32];
    __shared__ float red[32][8];
    __shared__ float pooled[32];

    if (t < 32){
        const double N = (double)BATCH * (double)LSEQ;
        { double S = g_stat[0][0][t], Q = g_stat[0][1][t];
          double m = S/N, v = Q/N - m*m;
          double s = (double)gamma1[t] / sqrt(v + EPSBN);
          sc0[t] = (float)s; sh0[t] = (float)((double)beta1[t] - m*s); }
        { double S = g_stat[2][0][t], Q = g_stat[2][1][t];
          double m = S/N, v = Q/N - m*m;
          double s = (double)gamma3[t] / sqrt(v + EPSBN);
          sc2[t] = (float)s; sh2[t] = (float)((double)beta3[t] - m*s); }
    }
    __syncthreads();

    const float* p1 = g_buf1 + (size_t)b*CH*LSEQ;
    const float* p2 = g_buf3 + (size_t)b*CH*LSEQ;
    const int wid = t >> 5, lane = t & 31;
#pragma unroll 1
    for (int c = 0; c < 32; c++){
        float y1 = p1[c*LSEQ + t];
        float h2 = p2[c*LSEQ + t];
        float x1 = fmaxf(sc0[c]*y1 + sh0[c], 0.f);
        float x2 = fmaxf(sc2[c]*h2 + sh2[c] + x1, 0.f);
        float s = wred32(x2);
        if (lane == 0) red[c][wid] = s;
    }
    __syncthreads();
    if (t < 32){
        float s = 0.f;
#pragma unroll
        for (int wI = 0; wI < 8; wI++) s += red[t][wI];
        pooled[t] = s * (1.f/(float)LSEQ);
    }
    __syncthreads();
    if (t < 64){
        float acc = lin_b[t];
#pragma unroll
        for (int c = 0; c < 32; c++) acc += pooled[c]*lin_w[c*64 + t];
        g_ctx[(size_t)b*64 + t] = tanhf(acc);
    }
}

// ---------------- K5: 10 coupling layers, 64 rows per block ---------------
// Weight loads batched 8-deep (MLP=8) to hide L2 latency.
__global__ __launch_bounds__(256) void k_coupling(const float* __restrict__ zin,
                                                  const float* __restrict__ W1,
                                                  const float* __restrict__ B1w,
                                                  const float* __restrict__ W2,
                                                  const float* __restrict__ B2w,
                                                  const float* __restrict__ W3,
                                                  const float* __restrict__ B3w,
                                                  float* __restrict__ outp){
    const int t = threadIdx.x;
    const int rowBase = blockIdx.x * 64;
    extern __shared__ float sm[];
    float* nin = sm;                 // 64*76
    float* hA  = nin + 64*76;        // 64*132
    float* hB  = hA  + 64*132;       // 64*132
    float* zz  = hB  + 64*132;       // 64*12
    float* ob  = zz  + 64*12;        // 64*20
    float* ldv = ob  + 64*20;        // 64

    for (int idx = t; idx < 64*9; idx += 256){
        int r = idx/9, j = idx - r*9;
        zz[r*12 + j] = zin[(size_t)(rowBase + r)*9 + j];
    }
    for (int idx = t; idx < 64*64; idx += 256){
        int r = idx >> 6, j = idx & 63;
        nin[r*76 + 9 + j] = g_ctx[(size_t)(rowBase + r)*64 + j];
    }
    if (t < 64) ldv[t] = 0.f;
    __syncthreads();

    const int jc = t & 31;           // 4 output columns: 4*jc .. 4*jc+3
    const int r0 = (t >> 5) * 8;     // 8 rows per warp

    for (int layer = 0; layer < 10; ++layer){
        if (t < 64){
#pragma unroll
            for (int j = 0; j < 9; j++){
                float m = (((j + layer) & 1) == 0) ? 1.f : 0.f;
                nin[t*76 + j] = zz[t*12 + j] * m;
            }
        }
        __syncthreads();

        // GEMM1: hA = relu(nin[64x73] @ W1[73x128] + b1)  (packed f32x2)
        {
            const float* Wl = W1 + (size_t)layer*73*128;
            float4 bb = *(const float4*)(B1w + layer*128 + 4*jc);
            ull acc[8][2];
#pragma unroll
            for (int r = 0; r < 8; r++){ acc[r][0] = pk(bb.x, bb.y); acc[r][1] = pk(bb.z, bb.w); }
#pragma unroll 1
            for (int i0 = 0; i0 < 64; i0 += 8){
                ulonglong2 wv[8];
#pragma unroll
                for (int u = 0; u < 8; u++)
                    wv[u] = *(const ulonglong2*)(Wl + (i0 + u)*128 + 4*jc);
#pragma unroll
                for (int u = 0; u < 8; u++){
#pragma unroll
                    for (int r = 0; r < 8; r++){
                        float x = nin[(r0 + r)*76 + i0 + u];
                        ull xx = pk(x, x);
                        ffma2_acc(acc[r][0], xx, wv[u].x);
                        ffma2_acc(acc[r][1], xx, wv[u].y);
                    }
                }
            }
            {   // tail i = 64..72 (9 iters), batched load
                ulonglong2 wv[9];
#pragma unroll
                for (int u = 0; u < 9; u++)
                    wv[u] = *(const ulonglong2*)(Wl + (64 + u)*128 + 4*jc);
#pragma unroll
                for (int u = 0; u < 9; u++){
#pragma unroll
                    for (int r = 0; r < 8; r++){
                        float x = nin[(r0 + r)*76 + 64 + u];
                        ull xx = pk(x, x);
                        ffma2_acc(acc[r][0], xx, wv[u].x);
                        ffma2_acc(acc[r][1], xx, wv[u].y);
                    }
                }
            }
#pragma unroll
            for (int r = 0; r < 8; r++){
                float v0,v1,v2,v3;
                upk(acc[r][0], v0, v1); upk(acc[r][1], v2, v3);
                *(float4*)(hA + (r0 + r)*132 + 4*jc) =
                    make_float4(fmaxf(v0,0.f), fmaxf(v1,0.f), fmaxf(v2,0.f), fmaxf(v3,0.f));
            }
        }
        __syncthreads();

        // GEMM2: hB = relu(hA[64x128] @ W2[128x128] + b2)  (packed f32x2)
        {
            const float* Wl = W2 + (size_t)layer*128*128;
            float4 bb = *(const float4*)(B2w + layer*128 + 4*jc);
            ull acc[8][2];
#pragma unroll
            for (int r = 0; r < 8; r++){ acc[r][0] = pk(bb.x, bb.y); acc[r][1] = pk(bb.z, bb.w); }
#pragma unroll 1
            for (int i0 = 0; i0 < 128; i0 += 8){
                ulonglong2 wv[8];
#pragma unroll
                for (int u = 0; u < 8; u++)
                    wv[u] = *(const ulonglong2*)(Wl + (i0 + u)*128 + 4*jc);
#pragma unroll
                for (int u = 0; u < 8; u++){
#pragma unroll
                    for (int r = 0; r < 8; r++){
                        float x = hA[(r0 + r)*132 + i0 + u];
                        ull xx = pk(x, x);
                        ffma2_acc(acc[r][0], xx, wv[u].x);
                        ffma2_acc(acc[r][1], xx, wv[u].y);
                    }
                }
            }
#pragma unroll
            for (int r = 0; r < 8; r++){
                float v0,v1,v2,v3;
                upk(acc[r][0], v0, v1); upk(acc[r][1], v2, v3);
                *(float4*)(hB + (r0 + r)*132 + 4*jc) =
                    make_float4(fmaxf(v0,0.f), fmaxf(v1,0.f), fmaxf(v2,0.f), fmaxf(v3,0.f));
            }
        }
        __syncthreads();

        // GEMM3: ob = hB[64x128] @ W3[128x18] + b3
        {
            const float* Wl = W3 + (size_t)layer*128*18;
            const int r = t >> 2, q = t & 3;
            float acc[5] = {0.f,0.f,0.f,0.f,0.f};
#pragma unroll 4
            for (int i = 0; i < 128; i++){
                float x = hB[r*132 + i];
#pragma unroll
                for (int k = 0; k < 5; k++){
                    int j = q + 4*k;
                    if (j < 18) acc[k] = fmaf(x, __ldg(Wl + i*18 + j), acc[k]);
                }
            }
#pragma unroll
            for (int k = 0; k < 5; k++){
                int j = q + 4*k;
                if (j < 18) ob[r*20 + j] = acc[k] + B3w[layer*18 + j];
            }
        }
        __syncthreads();

        // per-row flow update
        if (t < 64){
            float ldl = ldv[t];
#pragma unroll
            for (int j = 0; j < 9; j++){
                if (((j + layer) & 1) != 0){
                    float s  = tanhf(ob[t*20 + j]);
                    float tt = ob[t*20 + 9 + j];
                    zz[t*12 + j] = zz[t*12 + j]*expf(s) + tt;
                    ldl += s;
                }
            }
            ldv[t] = ldl;
        }
        __syncthreads();
    }

    if (t < 64){
        float lp = 0.f;
#pragma unroll
        for (int j = 0; j < 9; j++){
            float z = zz[t*12 + j];
            lp += LOG2PI + z*z;
        }
        outp[rowBase + t] = ldv[t] - 0.5f*lp;
    }
}

// ---------------- launch ----------------------------------------------------
extern "C" void kernel_launch(void* const* d_in, const int* in_sizes, int n_in,
                              void* d_out, int out_size){
    const float* inputs  = (const float*)d_in[0];
    const float* curve   = (const float*)d_in[1];
    const float* conv1_w = (const float*)d_in[2];
    const float* conv1_b = (const float*)d_in[3];
    const float* bn1_g   = (const float*)d_in[4];
    const float* bn1_b   = (const float*)d_in[5];
    const float* rb_w1   = (const float*)d_in[6];
    const float* rb_b1   = (const float*)d_in[7];
    const float* rb_g1   = (const float*)d_in[8];
    const float* rb_be1  = (const float*)d_in[9];
    const float* rb_w2   = (const float*)d_in[10];
    const float* rb_b2   = (const float*)d_in[11];
    const float* rb_g2   = (const float*)d_in[12];
    const float* rb_be2  = (const float*)d_in[13];
    const float* lin_w   = (const float*)d_in[14];
    const float* lin_b   = (const float*)d_in[15];
    const float* W1      = (const float*)d_in[16];
    const float* B1      = (const float*)d_in[17];
    const float* W2      = (const float*)d_in[18];
    const float* B2      = (const float*)d_in[19];
    const float* W3      = (const float*)d_in[20];
    const float* B3      = (const float*)d_in[21];
    float* out = (float*)d_out;

    const int smem1 = 1024*8 + (32 + 4*272 + 32 + 32) * 4;
    const int smemC = (64*76 + 64*132*2 + 64*12 + 64*20 + 64) * 4;

    cudaFuncSetAttribute(k_conv1,    cudaFuncAttributeMaxDynamicSharedMemorySize, smem1);
    cudaFuncSetAttribute(k_rbmma,    cudaFuncAttributeMaxDynamicSharedMemorySize, SM_TOTAL_M);
    cudaFuncSetAttribute(k_coupling, cudaFuncAttributeMaxDynamicSharedMemorySize, smemC);

    k_prep<<<1, 256>>>(rb_w1, rb_w2);
    k_conv1<<<BATCH, 128, smem1>>>(curve, conv1_w, conv1_b);
    k_rbmma<<<BATCH*2, 256, SM_TOTAL_M>>>(0, bn1_g, bn1_b, rb_b1);
    k_rbmma<<<BATCH*2, 256, SM_TOTAL_M>>>(1, rb_g1, rb_be1, rb_b2);
    k_pool_ctx<<<BATCH, 256>>>(bn1_g, bn1_b, rb_g2, rb_be2, lin_w, lin_b);
    k_coupling<<<BATCH/64, 256, smemC>>>(inputs, W1, B1, W2, B2, W3, B3, out);
}

// round 16
// speedup vs baseline: 1.2702x; 1.0654x over previous
#include <cuda_runtime.h>
#include <cuda_bf16.h>
#include <cstdint>

#define BATCH 16384
#define LSEQ  256
#define CH    32
#define EPSBN 1e-5
#define LOG2PI 1.8378770664093453f

typedef unsigned long long ull;

// ---------------- scratch (device-global; no runtime alloc allowed) -------
__device__ float  g_buf1[(size_t)BATCH*CH*LSEQ];   // conv1 output (pre-BN)
__device__ float  g_buf2[(size_t)BATCH*CH*LSEQ];   // h1 (pre-BN)
__device__ float  g_buf3[(size_t)BATCH*CH*LSEQ];   // h2 (pre-BN)
__device__ float  g_ctx [(size_t)BATCH*64];        // context vectors
__device__ double g_stat[3][2][32];                // [stage][sum|sumsq][channel]
__device__ uint2  g_frag[2][2][768];               // [pass][wh|wl][(ks6*4+tn)*32+lane]

// ---------------- packed fp32x2 helpers (FFMA2, conv1/coupling) ------------
__device__ __forceinline__ ull pk(float lo, float hi){
    ull r; asm("mov.b64 %0, {%1,%2};" : "=l"(r) : "f"(lo), "f"(hi)); return r;
}
__device__ __forceinline__ void upk(ull v, float& lo, float& hi){
    asm("mov.b64 {%0,%1}, %2;" : "=f"(lo), "=f"(hi) : "l"(v));
}
__device__ __forceinline__ void ffma2_acc(ull& a, ull b, ull c){
    asm("fma.rn.f32x2 %0, %1, %2, %0;" : "+l"(a) : "l"(b), "l"(c));
}
__device__ __forceinline__ float wred32(float v){
#pragma unroll
    for (int o = 16; o > 0; o >>= 1) v += __shfl_xor_sync(0xffffffffu, v, o);
    return v;
}
__device__ __forceinline__ uint32_t smem_u32(const void* p){
    uint32_t a;
    asm("{ .reg .u64 t; cvta.to.shared.u64 t, %1; cvt.u32.u64 %0, t; }" : "=r"(a) : "l"(p));
    return a;
}

// ---------------- warp-MMA helpers (baseline PTX, works on sm_103) --------
#define LDMATRIX_X4(a0,a1,a2,a3, addr) \
    asm volatile("ldmatrix.sync.aligned.m8n8.x4.shared.b16 {%0,%1,%2,%3}, [%4];" \
        : "=r"(a0), "=r"(a1), "=r"(a2), "=r"(a3) : "r"(addr))
#define LDS64V(x0,x1, addr) \
    asm volatile("ld.shared.v2.u32 {%0,%1}, [%2];" : "=r"(x0), "=r"(x1) : "r"(addr))
#define MMA16816(d, a0,a1,a2,a3, b0,b1) \
    asm volatile("mma.sync.aligned.m16n8k16.row.col.f32.bf16.bf16.f32 " \
        "{%0,%1,%2,%3}, {%4,%5,%6,%7}, {%8,%9}, {%0,%1,%2,%3};" \
        : "+f"((d)[0]), "+f"((d)[1]), "+f"((d)[2]), "+f"((d)[3]) \
        : "r"(a0), "r"(a1), "r"(a2), "r"(a3), "r"(b0), "r"(b1))

// x buffer: 131 rows x 144 bytes (32 xh bf16 | 32 xl bf16, 16B pad)
#define STRXB 144
// smem byte offsets for k_rbmma (R11 layout)
#define SMX    0            // 131*144 = 18864
#define SMWHF  18864        // 768 uint2 = 6144
#define SMWLF  25008        // 6144
#define SMSC   31152        // sc[32], sh[32], cbs[32] = 384
#define SMRED  31536        // redS[8][32], redQ[8][32] = 2048
#define SM_TOTAL_M 33584

// ---------------- K0: zero stats + pre-pack B fragments --------------------
__global__ void k_prep(const float* __restrict__ w1, const float* __restrict__ w2){
    const int t = threadIdx.x;
    if (t < 192) (&g_stat[0][0][0])[t] = 0.0;
#pragma unroll 1
    for (int pass = 0; pass < 2; pass++){
        const float* w = pass ? w2 : w1;
        for (int idx = t; idx < 768; idx += 256){
            int ks6 = idx >> 7, rem = idx & 127, tn = rem >> 5, lane = rem & 31;
            int n = tn*8 + (lane >> 2);
            int kb = ks6*16 + (lane & 3)*2;
            float v[4];
#pragma unroll
            for (int e = 0; e < 4; e++){
                int k = kb + (e >> 1)*8 + (e & 1);      // kb, kb+1, kb+8, kb+9
                int i = k & 31, kkb = k >> 5;
                v[e] = w[n*96 + i*3 + kkb];
            }
            uint32_t h0, h1, l0, l1;
            float hh[4], ll[4];
#pragma unroll
            for (int e = 0; e < 4; e++){
                __nv_bfloat16 h = __float2bfloat16(v[e]);
                hh[e] = __bfloat162float(h);
                ll[e] = v[e] - hh[e];
            }
            asm("cvt.rn.bf16x2.f32 %0, %1, %2;" : "=r"(h0) : "f"(hh[1]), "f"(hh[0]));
            asm("cvt.rn.bf16x2.f32 %0, %1, %2;" : "=r"(h1) : "f"(hh[3]), "f"(hh[2]));
            asm("cvt.rn.bf16x2.f32 %0, %1, %2;" : "=r"(l0) : "f"(ll[1]), "f"(ll[0]));
            asm("cvt.rn.bf16x2.f32 %0, %1, %2;" : "=r"(l1) : "f"(ll[3]), "f"(ll[2]));
            g_frag[pass][0][idx] = make_uint2(h0, h1);
            g_frag[pass][1][idx] = make_uint2(l0, l1);
        }
    }
}

// ---------------- K1: conv1 (4->32, k=5, SAME) + bias, stats stage 0 -------
// 256 threads: warp -> 8 channels (wrp&3) x half-L (wrp>>2); lane -> 4 L
__global__ __launch_bounds__(256) void k_conv1(const float* __restrict__ curve,
                                               const float* __restrict__ w,
                                               const float* __restrict__ bias){
    const int b = blockIdx.x;
    const int t = threadIdx.x;
    extern __shared__ ull smu[];
    ull*   wd  = smu;                     // dup weights: ull[(i*32+c)*8 + k], 1024
    float* cbs = (float*)(wd + 1024);
    float* xin = cbs + 32;                // 4*272
    float* redS= xin + 4*272;             // [2][32]
    float* redQ= redS + 64;               // [2][32]

    if (t < 32) cbs[t] = bias[t];
    for (int idx = t; idx < 4*272; idx += 256){
        int i = idx / 272, p = idx - i*272, l = p - 2;
        xin[idx] = (l >= 0 && l < LSEQ) ? curve[((size_t)b*4 + i)*LSEQ + l] : 0.f;
    }
    for (int idx = t; idx < 4*32*8; idx += 256){
        int i = idx >> 8, rem = idx & 255, c = rem >> 3, k = rem & 7;
        float v = (k < 5) ? w[c*20 + i*5 + k] : 0.f;
        ((float2*)wd)[idx] = make_float2(v, v);
    }
    __syncthreads();

    const int wrp = t >> 5, lane = t & 31;
    const int c0 = (wrp & 3)*8, half = wrp >> 2;
    const int l0 = half*128 + lane*4;

    ull A[8][2];
#pragma unroll
    for (int cc = 0; cc < 8; cc++){
        float cb = cbs[c0 + cc];
        A[cc][0] = pk(cb, cb);
        A[cc][1] = pk(cb, cb);
    }
#pragma unroll
    for (int i = 0; i < 4; i++){
        const float* xb = xin + i*272 + l0;   // xb[0] = x_{l0-2}
        float4 u0 = *(const float4*)(xb);
        float4 u1 = *(const float4*)(xb + 4);
        float xm[8] = {u0.x,u0.y,u0.z,u0.w, u1.x,u1.y,u1.z,u1.w};
        ull P[7];
#pragma unroll
        for (int m = 0; m < 7; m++) P[m] = pk(xm[m], xm[m+1]);
        const ull* wp = wd + (i*32 + c0)*8;
#pragma unroll
        for (int cc = 0; cc < 8; cc++){
            ulonglong2 W01 = *(const ulonglong2*)(wp + cc*8);
            ulonglong2 W23 = *(const ulonglong2*)(wp + cc*8 + 2);
            ull W4 = wp[cc*8 + 4];
#pragma unroll
            for (int p = 0; p < 2; p++){
                ffma2_acc(A[cc][p], P[2*p+0], W01.x);
                ffma2_acc(A[cc][p], P[2*p+1], W01.y);
                ffma2_acc(A[cc][p], P[2*p+2], W23.x);
                ffma2_acc(A[cc][p], P[2*p+3], W23.y);
                ffma2_acc(A[cc][p], P[2*p+4], W4);
            }
        }
    }

    float* outp = g_buf1 + (size_t)b*CH*LSEQ;
#pragma unroll
    for (int cc = 0; cc < 8; cc++){
        float v[4];
        upk(A[cc][0], v[0], v[1]);
        upk(A[cc][1], v[2], v[3]);
        int c = c0 + cc;
        *(float4*)(outp + c*LSEQ + l0) = make_float4(v[0],v[1],v[2],v[3]);
        float s = 0.f, q = 0.f;
#pragma unroll
        for (int m = 0; m < 4; m++){ s += v[m]; q += v[m]*v[m]; }
        s = wred32(s); q = wred32(q);
        if (lane == 0){ redS[half*32 + c] = s; redQ[half*32 + c] = q; }
    }
    __syncthreads();
    if (t < 32){
        atomicAdd(&g_stat[0][0][t], (double)(redS[t] + redS[32 + t]));
        atomicAdd(&g_stat[0][1][t], (double)(redQ[t] + redQ[32 + t]));
    }
}

// ---------------- K2/K3: bn+relu -> conv(32->32,k3) via HMMA (R11 config) --
__global__ __launch_bounds__(256, 4) void k_rbmma(int pass,
                                               const float* __restrict__ gam,
                                               const float* __restrict__ bet,
                                               const float* __restrict__ cbias){
    const int b = blockIdx.x >> 1;
    const int lbase = (blockIdx.x & 1) * 128;
    const int t = threadIdx.x;
    const int lane = t & 31, wrp = t >> 5;
    const float* bufIn = (pass == 0) ? g_buf1 : g_buf2;
    float* bufOut = (pass == 0) ? g_buf2 : g_buf3;
    const int stIn = pass, stOut = pass + 1;

    extern __shared__ char smc[];
    const uint32_t smb = smem_u32(smc);
    float* sc  = (float*)(smc + SMSC);
    float* sh  = sc + 32;
    float* cbs = sh + 32;
    float* redS= (float*)(smc + SMRED);
    float* redQ= redS + 256;

    if (t < 32){
        const double N = (double)BATCH * (double)LSEQ;
        double S = g_stat[stIn][0][t], Q = g_stat[stIn][1][t];
        double m = S / N, v = Q / N - m*m;
        double s = (double)gam[t] / sqrt(v + EPSBN);
        sc[t] = (float)s;
        sh[t] = (float)((double)bet[t] - m*s);
        cbs[t] = cbias[t];
    }
    {
        const uint4* src = (const uint4*)&g_frag[pass][0][0];
        uint4* dst = (uint4*)(smc + SMWHF);
#pragma unroll
        for (int i = 0; i < 3; i++) dst[t + i*256] = src[t + i*256];
    }
    __syncthreads();

    {
        const float* inp = bufIn + (size_t)b*CH*LSEQ;
        for (int idx = t; idx < 16*130; idx += 256){
            int ip = idx / 130, lp = idx - ip*130;
            int i = ip*2;
            int l = lbase + lp - 1;
            float y0 = 0.f, y1 = 0.f;
            if (l >= 0 && l < LSEQ){
                y0 = fmaxf(sc[i]*inp[i*LSEQ + l] + sh[i], 0.f);
                y1 = fmaxf(sc[i+1]*inp[(i+1)*LSEQ + l] + sh[i+1], 0.f);
            }
            uint32_t hp;
            asm("cvt.rn.bf16x2.f32 %0, %1, %2;" : "=r"(hp) : "f"(y1), "f"(y0));
            float h0 = __uint_as_float(hp << 16);
            float h1 = __uint_as_float(hp & 0xffff0000u);
            float e0 = y0 - h0, e1 = y1 - h1;
            uint32_t lp2;
            asm("cvt.rn.bf16x2.f32 %0, %1, %2;" : "=r"(lp2) : "f"(e1), "f"(e0));
            *(uint32_t*)(smc + SMX + lp*STRXB + i*2)      = hp;
            *(uint32_t*)(smc + SMX + lp*STRXB + 64 + i*2) = lp2;
        }
    }
    __syncthreads();

    const int m0 = wrp*16;
    float d[4][4];
#pragma unroll
    for (int tn = 0; tn < 4; tn++)
#pragma unroll
        for (int e = 0; e < 4; e++) d[tn][e] = 0.f;

    const uint32_t axbase = smb + SMX +
        (uint32_t)((m0 + (lane & 15))*STRXB + ((lane & 16) ? 16 : 0));
    const uint32_t bwh = smb + SMWHF + (uint32_t)(lane*8);
    const uint32_t bwl = smb + SMWLF + (uint32_t)(lane*8);

#pragma unroll
    for (int ks6 = 0; ks6 < 6; ks6++){
        const int kk = ks6 >> 1, kc = ks6 & 1;
        const uint32_t aaddr = axbase + (uint32_t)(kk*STRXB + kc*32);
        uint32_t ah0,ah1,ah2,ah3, al0,al1,al2,al3;
        LDMATRIX_X4(ah0,ah1,ah2,ah3, aaddr);          // xh
        LDMATRIX_X4(al0,al1,al2,al3, aaddr + 64);     // xl
        uint32_t b00,b01,b10,b11,b20,b21,b30,b31;
        LDS64V(b00,b01, bwh + (uint32_t)((ks6*4 + 0)*256));
        LDS64V(b10,b11, bwh + (uint32_t)((ks6*4 + 1)*256));
        LDS64V(b20,b21, bwh + (uint32_t)((ks6*4 + 2)*256));
        LDS64V(b30,b31, bwh + (uint32_t)((ks6*4 + 3)*256));
        MMA16816(d[0], ah0,ah1,ah2,ah3, b00,b01);     // xh @ wh
        MMA16816(d[1], ah0,ah1,ah2,ah3, b10,b11);
        MMA16816(d[2], ah0,ah1,ah2,ah3, b20,b21);
        MMA16816(d[3], ah0,ah1,ah2,ah3, b30,b31);
        MMA16816(d[0], al0,al1,al2,al3, b00,b01);     // xl @ wh
        MMA16816(d[1], al0,al1,al2,al3, b10,b11);
        MMA16816(d[2], al0,al1,al2,al3, b20,b21);
        MMA16816(d[3], al0,al1,al2,al3, b30,b31);
        LDS64V(b00,b01, bwl + (uint32_t)((ks6*4 + 0)*256));
        LDS64V(b10,b11, bwl + (uint32_t)((ks6*4 + 1)*256));
        LDS64V(b20,b21, bwl + (uint32_t)((ks6*4 + 2)*256));
        LDS64V(b30,b31, bwl + (uint32_t)((ks6*4 + 3)*256));
        MMA16816(d[0], ah0,ah1,ah2,ah3, b00,b01);     // xh @ wl
        MMA16816(d[1], ah0,ah1,ah2,ah3, b10,b11);
        MMA16816(d[2], ah0,ah1,ah2,ah3, b20,b21);
        MMA16816(d[3], ah0,ah1,ah2,ah3, b30,b31);
    }

    float* outp = bufOut + (size_t)b*CH*LSEQ + lbase;
    float ps[8], pq[8];
#pragma unroll
    for (int j = 0; j < 8; j++){ ps[j] = 0.f; pq[j] = 0.f; }
    {
        int r0 = m0 + (lane >> 2);
#pragma unroll
        for (int tn = 0; tn < 4; tn++){
            int c0 = tn*8 + (lane & 3)*2;
            float v00 = d[tn][0] + cbs[c0];
            float v01 = d[tn][1] + cbs[c0+1];
            float v10 = d[tn][2] + cbs[c0];
            float v11 = d[tn][3] + cbs[c0+1];
            outp[c0*LSEQ + r0]         = v00;
            outp[(c0+1)*LSEQ + r0]     = v01;
            outp[c0*LSEQ + r0 + 8]     = v10;
            outp[(c0+1)*LSEQ + r0 + 8] = v11;
            ps[tn*2+0] += v00 + v10;  pq[tn*2+0] += v00*v00 + v10*v10;
            ps[tn*2+1] += v01 + v11;  pq[tn*2+1] += v01*v01 + v11*v11;
        }
    }
#pragma unroll
    for (int j = 0; j < 8; j++){
#pragma unroll
        for (int o = 4; o < 32; o <<= 1){
            ps[j] += __shfl_xor_sync(0xffffffffu, ps[j], o);
            pq[j] += __shfl_xor_sync(0xffffffffu, pq[j], o);
        }
    }
    if (lane < 4){
#pragma unroll
        for (int tn = 0; tn < 4; tn++){
#pragma unroll
            for (int p = 0; p < 2; p++){
                int c = tn*8 + lane*2 + p;
                redS[wrp*32 + c] = ps[tn*2+p];
                redQ[wrp*32 + c] = pq[tn*2+p];
            }
        }
    }
    __syncthreads();
    if (t < 32){
        double S = 0.0, Q = 0.0;
#pragma unroll
        for (int wI = 0; wI < 8; wI++){ S += redS[wI*32 + t]; Q += redQ[wI*32 + t]; }
        atomicAdd(&g_stat[stOut][0][t], S);
        atomicAdd(&g_stat[stOut][1][t], Q);
    }
}

// ---------------- K4: bn0+relu, bn2, residual+relu, mean-pool, linear+tanh -
__global__ __launch_bounds__(256) void k_pool_ctx(const float* __restrict__ gamma1,
                                                  const float* __restrict__ beta1,
                                                  const float* __restrict__ gamma3,
                                                  const float* __restrict__ beta3,
                                                  const float* __restrict__ lin_w,
                                                  const float* __restrict__ lin_b){
    const int b = blockIdx.x;
    const int t = threadIdx.x;
    __shared__ float sc0[32], sh0[32], sc2[32], sh2[32];
    __shared__ float red[32][8];
    __shared__ float pooled[32];

    if (t < 32){
        const double N = (double)BATCH * (double)LSEQ;
        { double S = g_stat[0][0][t], Q = g_stat[0][1][t];
          double m = S/N, v = Q/N - m*m;
          double s = (double)gamma1[t] / sqrt(v + EPSBN);
          sc0[t] = (float)s; sh0[t] = (float)((double)beta1[t] - m*s); }
        { double S = g_stat[2][0][t], Q = g_stat[2][1][t];
          double m = S/N, v = Q/N - m*m;
          double s = (double)gamma3[t] / sqrt(v + EPSBN);
          sc2[t] = (float)s; sh2[t] = (float)((double)beta3[t] - m*s); }
    }
    __syncthreads();

    const float* p1 = g_buf1 + (size_t)b*CH*LSEQ;
    const float* p2 = g_buf3 + (size_t)b*CH*LSEQ;
    const int wid = t >> 5, lane = t & 31;
#pragma unroll 1
    for (int c = 0; c < 32; c++){
        float y1 = p1[c*LSEQ + t];
        float h2 = p2[c*LSEQ + t];
        float x1 = fmaxf(sc0[c]*y1 + sh0[c], 0.f);
        float x2 = fmaxf(sc2[c]*h2 + sh2[c] + x1, 0.f);
        float s = wred32(x2);
        if (lane == 0) red[c][wid] = s;
    }
    __syncthreads();
    if (t < 32){
        float s = 0.f;
#pragma unroll
        for (int wI = 0; wI < 8; wI++) s += red[t][wI];
        pooled[t] = s * (1.f/(float)LSEQ);
    }
    __syncthreads();
    if (t < 64){
        float acc = lin_b[t];
#pragma unroll
        for (int c = 0; c < 32; c++) acc += pooled[c]*lin_w[c*64 + t];
        g_ctx[(size_t)b*64 + t] = tanhf(acc);
    }
}

// ---------------- K5: 10 coupling layers, 64 rows per block ---------------
// GEMM1/2 weights batched 8-deep; W3 staged to smem per layer.
__global__ __launch_bounds__(256) void k_coupling(const float* __restrict__ zin,
                                                  const float* __restrict__ W1,
                                                  const float* __restrict__ B1w,
                                                  const float* __restrict__ W2,
                                                  const float* __restrict__ B2w,
                                                  const float* __restrict__ W3,
                                                  const float* __restrict__ B3w,
                                                  float* __restrict__ outp){
    const int t = threadIdx.x;
    const int rowBase = blockIdx.x * 64;
    extern __shared__ float sm[];
    float* nin = sm;                 // 64*76
    float* hA  = nin + 64*76;        // 64*132
    float* hB  = hA  + 64*132;       // 64*132
    float* zz  = hB  + 64*132;       // 64*12
    float* ob  = zz  + 64*12;        // 64*20
    float* ldv = ob  + 64*20;        // 64
    float* w3s = ldv + 64;           // 128*18 = 2304

    for (int idx = t; idx < 64*9; idx += 256){
        int r = idx/9, j = idx - r*9;
        zz[r*12 + j] = zin[(size_t)(rowBase + r)*9 + j];
    }
    for (int idx = t; idx < 64*64; idx += 256){
        int r = idx >> 6, j = idx & 63;
        nin[r*76 + 9 + j] = g_ctx[(size_t)(rowBase + r)*64 + j];
    }
    if (t < 64) ldv[t] = 0.f;
    __syncthreads();

    const int jc = t & 31;           // 4 output columns: 4*jc .. 4*jc+3
    const int r0 = (t >> 5) * 8;     // 8 rows per warp

    for (int layer = 0; layer < 10; ++layer){
        if (t < 64){
#pragma unroll
            for (int j = 0; j < 9; j++){
                float m = (((j + layer) & 1) == 0) ? 1.f : 0.f;
                nin[t*76 + j] = zz[t*12 + j] * m;
            }
        }
        // stage W3 layer slice to smem (visible at GEMM3 via intervening syncs)
        {
            const float* Wl3 = W3 + (size_t)layer*128*18;
            for (int idx = t; idx < 2304; idx += 256) w3s[idx] = Wl3[idx];
        }
        __syncthreads();

        // GEMM1: hA = relu(nin[64x73] @ W1[73x128] + b1)  (packed f32x2)
        {
            const float* Wl = W1 + (size_t)layer*73*128;
            float4 bb = *(const float4*)(B1w + layer*128 + 4*jc);
            ull acc[8][2];
#pragma unroll
            for (int r = 0; r < 8; r++){ acc[r][0] = pk(bb.x, bb.y); acc[r][1] = pk(bb.z, bb.w); }
#pragma unroll 1
            for (int i0 = 0; i0 < 64; i0 += 8){
                ulonglong2 wv[8];
#pragma unroll
                for (int u = 0; u < 8; u++)
                    wv[u] = *(const ulonglong2*)(Wl + (i0 + u)*128 + 4*jc);
#pragma unroll
                for (int u = 0; u < 8; u++){
#pragma unroll
                    for (int r = 0; r < 8; r++){
                        float x = nin[(r0 + r)*76 + i0 + u];
                        ull xx = pk(x, x);
                        ffma2_acc(acc[r][0], xx, wv[u].x);
                        ffma2_acc(acc[r][1], xx, wv[u].y);
                    }
                }
            }
            {   // tail i = 64..72 (9 iters), batched load
                ulonglong2 wv[9];
#pragma unroll
                for (int u = 0; u < 9; u++)
                    wv[u] = *(const ulonglong2*)(Wl + (64 + u)*128 + 4*jc);
#pragma unroll
                for (int u = 0; u < 9; u++){
#pragma unroll
                    for (int r = 0; r < 8; r++){
                        float x = nin[(r0 + r)*76 + 64 + u];
                        ull xx = pk(x, x);
                        ffma2_acc(acc[r][0], xx, wv[u].x);
                        ffma2_acc(acc[r][1], xx, wv[u].y);
                    }
                }
            }
#pragma unroll
            for (int r = 0; r < 8; r++){
                float v0,v1,v2,v3;
                upk(acc[r][0], v0, v1); upk(acc[r][1], v2, v3);
                *(float4*)(hA + (r0 + r)*132 + 4*jc) =
                    make_float4(fmaxf(v0,0.f), fmaxf(v1,0.f), fmaxf(v2,0.f), fmaxf(v3,0.f));
            }
        }
        __syncthreads();

        // GEMM2: hB = relu(hA[64x128] @ W2[128x128] + b2)  (packed f32x2)
        {
            const float* Wl = W2 + (size_t)layer*128*128;
            float4 bb = *(const float4*)(B2w + layer*128 + 4*jc);
            ull acc[8][2];
#pragma unroll
            for (int r = 0; r < 8; r++){ acc[r][0] = pk(bb.x, bb.y); acc[r][1] = pk(bb.z, bb.w); }
#pragma unroll 1
            for (int i0 = 0; i0 < 128; i0 += 8){
                ulonglong2 wv[8];
#pragma unroll
                for (int u = 0; u < 8; u++)
                    wv[u] = *(const ulonglong2*)(Wl + (i0 + u)*128 + 4*jc);
#pragma unroll
                for (int u = 0; u < 8; u++){
#pragma unroll
                    for (int r = 0; r < 8; r++){
                        float x = hA[(r0 + r)*132 + i0 + u];
                        ull xx = pk(x, x);
                        ffma2_acc(acc[r][0], xx, wv[u].x);
                        ffma2_acc(acc[r][1], xx, wv[u].y);
                    }
                }
            }
#pragma unroll
            for (int r = 0; r < 8; r++){
                float v0,v1,v2,v3;
                upk(acc[r][0], v0, v1); upk(acc[r][1], v2, v3);
                *(float4*)(hB + (r0 + r)*132 + 4*jc) =
                    make_float4(fmaxf(v0,0.f), fmaxf(v1,0.f), fmaxf(v2,0.f), fmaxf(v3,0.f));
            }
        }
        __syncthreads();

        // GEMM3: ob = hB[64x128] @ W3[128x18] + b3  (W3 from smem)
        {
            const int r = t >> 2, q = t & 3;
            float acc[5] = {0.f,0.f,0.f,0.f,0.f};
#pragma unroll 4
            for (int i = 0; i < 128; i++){
                float x = hB[r*132 + i];
#pragma unroll
                for (int k = 0; k < 5; k++){
                    int j = q + 4*k;
                    if (j < 18) acc[k] = fmaf(x, w3s[i*18 + j], acc[k]);
                }
            }
#pragma unroll
            for (int k = 0; k < 5; k++){
                int j = q + 4*k;
                if (j < 18) ob[r*20 + j] = acc[k] + B3w[layer*18 + j];
            }
        }
        __syncthreads();

        // per-row flow update
        if (t < 64){
            float ldl = ldv[t];
#pragma unroll
            for (int j = 0; j < 9; j++){
                if (((j + layer) & 1) != 0){
                    float s  = tanhf(ob[t*20 + j]);
                    float tt = ob[t*20 + 9 + j];
                    zz[t*12 + j] = zz[t*12 + j]*expf(s) + tt;
                    ldl += s;
                }
            }
            ldv[t] = ldl;
        }
        __syncthreads();
    }

    if (t < 64){
        float lp = 0.f;
#pragma unroll
        for (int j = 0; j < 9; j++){
            float z = zz[t*12 + j];
            lp += LOG2PI + z*z;
        }
        outp[rowBase + t] = ldv[t] - 0.5f*lp;
    }
}

// ---------------- launch ----------------------------------------------------
extern "C" void kernel_launch(void* const* d_in, const int* in_sizes, int n_in,
                              void* d_out, int out_size){
    const float* inputs  = (const float*)d_in[0];
    const float* curve   = (const float*)d_in[1];
    const float* conv1_w = (const float*)d_in[2];
    const float* conv1_b = (const float*)d_in[3];
    const float* bn1_g   = (const float*)d_in[4];
    const float* bn1_b   = (const float*)d_in[5];
    const float* rb_w1   = (const float*)d_in[6];
    const float* rb_b1   = (const float*)d_in[7];
    const float* rb_g1   = (const float*)d_in[8];
    const float* rb_be1  = (const float*)d_in[9];
    const float* rb_w2   = (const float*)d_in[10];
    const float* rb_b2   = (const float*)d_in[11];
    const float* rb_g2   = (const float*)d_in[12];
    const float* rb_be2  = (const float*)d_in[13];
    const float* lin_w   = (const float*)d_in[14];
    const float* lin_b   = (const float*)d_in[15];
    const float* W1      = (const float*)d_in[16];
    const float* B1      = (const float*)d_in[17];
    const float* W2      = (const float*)d_in[18];
    const float* B2      = (const float*)d_in[19];
    const float* W3      = (const float*)d_in[20];
    const float* B3      = (const float*)d_in[21];
    float* out = (float*)d_out;

    const int smem1 = 1024*8 + (32 + 4*272 + 64 + 64) * 4;
    const int smemC = (64*76 + 64*132*2 + 64*12 + 64*20 + 64 + 2304) * 4;

    cudaFuncSetAttribute(k_conv1,    cudaFuncAttributeMaxDynamicSharedMemorySize, smem1);
    cudaFuncSetAttribute(k_rbmma,    cudaFuncAttributeMaxDynamicSharedMemorySize, SM_TOTAL_M);
    cudaFuncSetAttribute(k_coupling, cudaFuncAttributeMaxDynamicSharedMemorySize, smemC);

    k_prep<<<1, 256>>>(rb_w1, rb_w2);
    k_conv1<<<BATCH, 256, smem1>>>(curve, conv1_w, conv1_b);
    k_rbmma<<<BATCH*2, 256, SM_TOTAL_M>>>(0, bn1_g, bn1_b, rb_b1);
    k_rbmma<<<BATCH*2, 256, SM_TOTAL_M>>>(1, rb_g1, rb_be1, rb_b2);
    k_pool_ctx<<<BATCH, 256>>>(bn1_g, bn1_b, rb_g2, rb_be2, lin_w, lin_b);
    k_coupling<<<BATCH/64, 256, smemC>>>(inputs, W1, B1, W2, B2, W3, B3, out);
}